// round 1
// baseline (speedup 1.0000x reference)
#include <cuda_runtime.h>

// Problem constants
#define B_   8
#define K_   8
#define T_   2048
#define CS_  512
#define CH_  128
#define DIM_ 1024

#define TTILE   128     // t per block in kernel A
#define CSTILE  64      // cs per smem tile
#define WS_STR  132     // padded w-tile row stride (floats) -> conflict-free
#define NTHR    256

// Scratch (allocation-free rule: device globals)
__device__ int g_idx[B_ * K_ * T_];       // 512 KB
__device__ int g_counts[K_ * CS_];        // 16 KB

// ---------- packed f32x2 helpers ----------
__device__ __forceinline__ unsigned long long pack2(float a, float b) {
    unsigned long long r;
    asm("mov.b64 %0, {%1, %2};" : "=l"(r) : "r"(__float_as_uint(a)), "r"(__float_as_uint(b)));
    return r;
}
__device__ __forceinline__ unsigned long long ffma2(unsigned long long a,
                                                    unsigned long long b,
                                                    unsigned long long c) {
    unsigned long long d;
    asm("fma.rn.f32x2 %0, %1, %2, %3;" : "=l"(d) : "l"(a), "l"(b), "l"(c));
    return d;
}
__device__ __forceinline__ void unpack2(unsigned long long v, float& lo, float& hi) {
    unsigned ulo, uhi;
    asm("mov.b64 {%0, %1}, %2;" : "=r"(ulo), "=r"(uhi) : "l"(v));
    lo = __uint_as_float(ulo);
    hi = __uint_as_float(uhi);
}

__device__ __forceinline__ float gumbelf(float u) {
    // matches reference: -log(-log(u + 1e-10) + 1e-10), TEMP = 1
    return -logf(-logf(u + 1e-10f) + 1e-10f);
}

// ---------- kernel 0: zero histogram ----------
__global__ void zero_counts_kernel() {
    for (int i = threadIdx.x; i < K_ * CS_; i += blockDim.x) g_counts[i] = 0;
}

// ---------- kernel A: logits + gumbel + argmax ----------
// grid: (T/TTILE=16, K=8, B=8), 256 threads
// smem: xs[128c][128t] (16384 f) + ws[64cs][132] (8448 f) = 99,328 B dynamic
__global__ void __launch_bounds__(NTHR, 2)
logits_argmax_kernel(const float* __restrict__ x,
                     const float* __restrict__ pw,
                     const float* __restrict__ pb,
                     const float* __restrict__ noise) {
    extern __shared__ float smem[];
    float* xs = smem;              // [c][t], stride 128
    float* ws = smem + CH_ * TTILE;  // [cs][c], stride WS_STR

    const int tb  = blockIdx.x * TTILE;
    const int k   = blockIdx.y;
    const int b   = blockIdx.z;
    const int tid = threadIdx.x;

    // load x tile: x[(b*DIM + k*CH + c)*T + tb + t]
    {
        const float* xg = x + ((size_t)b * DIM_ + (size_t)k * CH_) * T_ + tb;
        const int c0 = tid >> 5;
        const int t4 = (tid & 31) * 4;
#pragma unroll
        for (int c = c0; c < CH_; c += 8) {
            float4 v = *reinterpret_cast<const float4*>(xg + (size_t)c * T_ + t4);
            *reinterpret_cast<float4*>(&xs[c * TTILE + t4]) = v;
        }
    }

    const int tc = tid >> 4;   // 0..15 : cs-subgroup
    const int tt = tid & 15;   // 0..15 : t-subgroup (8 t's each)
    const int tg = tb + tt * 8;

    float bestv[8];
    int   besti[8];
#pragma unroll
    for (int j = 0; j < 8; ++j) { bestv[j] = -3.4e38f; besti[j] = 0; }

    for (int ct = 0; ct < CS_ / CSTILE; ++ct) {
        __syncthreads();
        // load w tile: pw[(k*CS + ct*64 + cs)*CH + c]
        {
            const float* wg = pw + ((size_t)k * CS_ + (size_t)ct * CSTILE) * CH_;
            const int cs0 = tid >> 5;
            const int c4  = (tid & 31) * 4;
#pragma unroll
            for (int cs = cs0; cs < CSTILE; cs += 8) {
                float4 v = *reinterpret_cast<const float4*>(wg + (size_t)cs * CH_ + c4);
                *reinterpret_cast<float4*>(&ws[cs * WS_STR + c4]) = v;
            }
        }
        __syncthreads();

        unsigned long long acc[4][4];
#pragma unroll
        for (int i = 0; i < 4; ++i)
#pragma unroll
            for (int j = 0; j < 4; ++j) acc[i][j] = 0ull;

        const float* wbase = ws + (tc * 4) * WS_STR;
        const float* xbase = xs + (tt << 3);

#pragma unroll 4
        for (int c = 0; c < CH_; ++c) {
            const float* xr = xbase + c * TTILE;
            unsigned long long x0 = *reinterpret_cast<const unsigned long long*>(xr + 0);
            unsigned long long x1 = *reinterpret_cast<const unsigned long long*>(xr + 2);
            unsigned long long x2 = *reinterpret_cast<const unsigned long long*>(xr + 4);
            unsigned long long x3 = *reinterpret_cast<const unsigned long long*>(xr + 6);
#pragma unroll
            for (int i = 0; i < 4; ++i) {
                float w = wbase[i * WS_STR + c];
                unsigned long long wp = pack2(w, w);
                acc[i][0] = ffma2(wp, x0, acc[i][0]);
                acc[i][1] = ffma2(wp, x1, acc[i][1]);
                acc[i][2] = ffma2(wp, x2, acc[i][2]);
                acc[i][3] = ffma2(wp, x3, acc[i][3]);
            }
        }

        // epilogue: bias + gumbel + running argmax
#pragma unroll
        for (int i = 0; i < 4; ++i) {
            const int cs = ct * CSTILE + tc * 4 + i;
            const float bias = pb[k * CS_ + cs];
            const float* np = noise + (((size_t)(b * K_ + k) * CS_ + cs) * T_ + tg);
            float4 na = *reinterpret_cast<const float4*>(np);
            float4 nb = *reinterpret_cast<const float4*>(np + 4);
            float nn[8] = {na.x, na.y, na.z, na.w, nb.x, nb.y, nb.z, nb.w};
#pragma unroll
            for (int j = 0; j < 4; ++j) {
                float v0, v1;
                unpack2(acc[i][j], v0, v1);
                v0 += bias + gumbelf(nn[2 * j]);
                v1 += bias + gumbelf(nn[2 * j + 1]);
                if (v0 > bestv[2 * j])     { bestv[2 * j]     = v0; besti[2 * j]     = cs; }
                if (v1 > bestv[2 * j + 1]) { bestv[2 * j + 1] = v1; besti[2 * j + 1] = cs; }
            }
        }
    }

    // reduce over the 16 cs-subgroups per t (reuse xs region)
    __syncthreads();
    float* rv = xs;                          // [128 t][16 tc]
    int*   ri = reinterpret_cast<int*>(xs + TTILE * 16);
#pragma unroll
    for (int j = 0; j < 8; ++j) {
        const int tl = tt * 8 + j;
        rv[tl * 16 + tc] = bestv[j];
        ri[tl * 16 + tc] = besti[j];
    }
    __syncthreads();

    if (tid < TTILE) {
        float bv = -3.4e38f;
        int   bi = 0;
#pragma unroll
        for (int m = 0; m < 16; ++m) {
            float v = rv[tid * 16 + m];
            int   id = ri[tid * 16 + m];
            if (v > bv || (v == bv && id < bi)) { bv = v; bi = id; }
        }
        const int t = tb + tid;
        g_idx[(b * K_ + k) * T_ + t] = bi;
        atomicAdd(&g_counts[k * CS_ + bi], 1);
    }
}

// ---------- kernel B: codebook gather with smem transpose ----------
// grid: (T/64=32, K=8, B=8), 256 threads
__global__ void __launch_bounds__(256)
gather_kernel(const float* __restrict__ cb, float* __restrict__ out) {
    __shared__ float sm[CH_ * 65];   // [c][t], stride 65 -> conflict-free both phases
    __shared__ int sidx[64];

    const int tb  = blockIdx.x * 64;
    const int k   = blockIdx.y;
    const int b   = blockIdx.z;
    const int tid = threadIdx.x;

    if (tid < 64) sidx[tid] = g_idx[(b * K_ + k) * T_ + tb + tid];
    __syncthreads();

    // load 64 codebook rows, scatter-transpose into smem (conflict-free)
    {
        const int c = tid & 127;
        const int rh = tid >> 7;   // 0..1
#pragma unroll 4
        for (int it = 0; it < 32; ++it) {
            const int r = it * 2 + rh;
            float v = cb[((size_t)k * CS_ + sidx[r]) * CH_ + c];
            sm[c * 65 + r] = v;
        }
    }
    __syncthreads();

    // coalesced writes along t
    {
        const int t  = tid & 63;
        const int c0 = tid >> 6;   // 0..3
        float* og = out + ((size_t)b * DIM_ + (size_t)k * CH_) * T_ + tb + t;
#pragma unroll 8
        for (int m = 0; m < 32; ++m) {
            const int c = c0 * 32 + m;
            og[(size_t)c * T_] = sm[c * 65 + t];
        }
    }
}

// ---------- kernel C: perplexity ----------
__global__ void perplexity_kernel(float* __restrict__ out) {
    const int k = blockIdx.x;
    const int lane = threadIdx.x;
    float s = 0.0f;
    for (int i = lane; i < CS_; i += 32) {
        float p = (float)g_counts[k * CS_ + i] * (1.0f / (B_ * T_));
        s += -p * logf(p + 1e-8f);   // p==0 contributes exactly 0 (matches nansum)
    }
#pragma unroll
    for (int o = 16; o; o >>= 1) s += __shfl_down_sync(0xffffffffu, s, o);
    if (lane == 0) out[(size_t)B_ * DIM_ * T_ + k] = expf(s);
}

extern "C" void kernel_launch(void* const* d_in, const int* in_sizes, int n_in,
                              void* d_out, int out_size) {
    const float* x     = (const float*)d_in[0];
    const float* pw    = (const float*)d_in[1];
    const float* pb    = (const float*)d_in[2];
    const float* cbk   = (const float*)d_in[3];
    const float* noise = (const float*)d_in[4];
    float* out = (float*)d_out;

    const int smemA = (CH_ * TTILE + CSTILE * WS_STR) * (int)sizeof(float);  // 99,328 B
    cudaFuncSetAttribute(logits_argmax_kernel,
                         cudaFuncAttributeMaxDynamicSharedMemorySize, smemA);

    zero_counts_kernel<<<1, 256>>>();
    logits_argmax_kernel<<<dim3(T_ / TTILE, K_, B_), NTHR, smemA>>>(x, pw, pb, noise);
    gather_kernel<<<dim3(T_ / 64, K_, B_), 256>>>(cbk, out);
    perplexity_kernel<<<K_, 32>>>(out);
}

// round 2
// speedup vs baseline: 1.6151x; 1.6151x over previous
#include <cuda_runtime.h>

// Problem constants
#define B_   8
#define K_   8
#define T_   2048
#define CS_  512
#define CH_  128
#define DIM_ 1024

#define TTILE   128     // t per block in kernel A
#define CSTILE  64      // cs per smem tile
#define WS_STR  132     // padded w-tile row stride (floats) -> conflict-free
#define NTHR    256

// Scratch (allocation-free rule: device globals)
__device__ int g_idx[B_ * K_ * T_];       // 512 KB
__device__ int g_counts[K_ * CS_];        // 16 KB

// ---------- packed f32x2 helpers ----------
__device__ __forceinline__ unsigned long long pack2(float a, float b) {
    unsigned long long r;
    asm("mov.b64 %0, {%1, %2};" : "=l"(r) : "r"(__float_as_uint(a)), "r"(__float_as_uint(b)));
    return r;
}
__device__ __forceinline__ unsigned long long ffma2(unsigned long long a,
                                                    unsigned long long b,
                                                    unsigned long long c) {
    unsigned long long d;
    asm("fma.rn.f32x2 %0, %1, %2, %3;" : "=l"(d) : "l"(a), "l"(b), "l"(c));
    return d;
}
__device__ __forceinline__ void unpack2(unsigned long long v, float& lo, float& hi) {
    unsigned ulo, uhi;
    asm("mov.b64 {%0, %1}, %2;" : "=r"(ulo), "=r"(uhi) : "l"(v));
    lo = __uint_as_float(ulo);
    hi = __uint_as_float(uhi);
}

__device__ __forceinline__ float gumbelf(float u) {
    // matches reference: -log(-log(u + 1e-10) + 1e-10), TEMP = 1
    return -logf(-logf(u + 1e-10f) + 1e-10f);
}

// ---------- kernel 0: zero histogram ----------
__global__ void zero_counts_kernel() {
    for (int i = threadIdx.x; i < K_ * CS_; i += blockDim.x) g_counts[i] = 0;
}

// ---------- kernel A: logits + gumbel + argmax ----------
// grid: (T/TTILE=16, K=8, B=8), 256 threads
// smem: xs[128c][128t] (16384 f) + ws[64cs][132] (8448 f) = 99,328 B dynamic
__global__ void __launch_bounds__(NTHR, 2)
logits_argmax_kernel(const float* __restrict__ x,
                     const float* __restrict__ pw,
                     const float* __restrict__ pb,
                     const float* __restrict__ noise) {
    extern __shared__ float smem[];
    float* xs = smem;              // [c][t], stride 128
    float* ws = smem + CH_ * TTILE;  // [cs][c], stride WS_STR

    const int tb  = blockIdx.x * TTILE;
    const int k   = blockIdx.y;
    const int b   = blockIdx.z;
    const int tid = threadIdx.x;

    // load x tile: x[(b*DIM + k*CH + c)*T + tb + t]
    {
        const float* xg = x + ((size_t)b * DIM_ + (size_t)k * CH_) * T_ + tb;
        const int c0 = tid >> 5;
        const int t4 = (tid & 31) * 4;
#pragma unroll
        for (int c = c0; c < CH_; c += 8) {
            float4 v = *reinterpret_cast<const float4*>(xg + (size_t)c * T_ + t4);
            *reinterpret_cast<float4*>(&xs[c * TTILE + t4]) = v;
        }
    }

    const int tc = tid >> 4;   // 0..15 : cs-subgroup
    const int tt = tid & 15;   // 0..15 : t-subgroup (8 t's each)
    const int tg = tb + tt * 8;

    float bestv[8];
    int   besti[8];
#pragma unroll
    for (int j = 0; j < 8; ++j) { bestv[j] = -3.4e38f; besti[j] = 0; }

    for (int ct = 0; ct < CS_ / CSTILE; ++ct) {
        __syncthreads();
        // load w tile: pw[(k*CS + ct*64 + cs)*CH + c]
        {
            const float* wg = pw + ((size_t)k * CS_ + (size_t)ct * CSTILE) * CH_;
            const int cs0 = tid >> 5;
            const int c4  = (tid & 31) * 4;
#pragma unroll
            for (int cs = cs0; cs < CSTILE; cs += 8) {
                float4 v = *reinterpret_cast<const float4*>(wg + (size_t)cs * CH_ + c4);
                *reinterpret_cast<float4*>(&ws[cs * WS_STR + c4]) = v;
            }
        }
        __syncthreads();

        unsigned long long acc[4][4];
#pragma unroll
        for (int i = 0; i < 4; ++i)
#pragma unroll
            for (int j = 0; j < 4; ++j) acc[i][j] = 0ull;

        const float* wbase = ws + (tc * 4) * WS_STR;
        const float* xbase = xs + (tt << 3);

#pragma unroll 4
        for (int c = 0; c < CH_; ++c) {
            const float* xr = xbase + c * TTILE;
            unsigned long long x0 = *reinterpret_cast<const unsigned long long*>(xr + 0);
            unsigned long long x1 = *reinterpret_cast<const unsigned long long*>(xr + 2);
            unsigned long long x2 = *reinterpret_cast<const unsigned long long*>(xr + 4);
            unsigned long long x3 = *reinterpret_cast<const unsigned long long*>(xr + 6);
#pragma unroll
            for (int i = 0; i < 4; ++i) {
                float w = wbase[i * WS_STR + c];
                unsigned long long wp = pack2(w, w);
                acc[i][0] = ffma2(wp, x0, acc[i][0]);
                acc[i][1] = ffma2(wp, x1, acc[i][1]);
                acc[i][2] = ffma2(wp, x2, acc[i][2]);
                acc[i][3] = ffma2(wp, x3, acc[i][3]);
            }
        }

        // epilogue: bias + gumbel + running argmax
#pragma unroll
        for (int i = 0; i < 4; ++i) {
            const int cs = ct * CSTILE + tc * 4 + i;
            const float bias = pb[k * CS_ + cs];
            const float* np = noise + (((size_t)(b * K_ + k) * CS_ + cs) * T_ + tg);
            float4 na = *reinterpret_cast<const float4*>(np);
            float4 nb = *reinterpret_cast<const float4*>(np + 4);
            float nn[8] = {na.x, na.y, na.z, na.w, nb.x, nb.y, nb.z, nb.w};
#pragma unroll
            for (int j = 0; j < 4; ++j) {
                float v0, v1;
                unpack2(acc[i][j], v0, v1);
                v0 += bias + gumbelf(nn[2 * j]);
                v1 += bias + gumbelf(nn[2 * j + 1]);
                if (v0 > bestv[2 * j])     { bestv[2 * j]     = v0; besti[2 * j]     = cs; }
                if (v1 > bestv[2 * j + 1]) { bestv[2 * j + 1] = v1; besti[2 * j + 1] = cs; }
            }
        }
    }

    // reduce over the 16 cs-subgroups per t (reuse xs region)
    __syncthreads();
    float* rv = xs;                          // [128 t][16 tc]
    int*   ri = reinterpret_cast<int*>(xs + TTILE * 16);
#pragma unroll
    for (int j = 0; j < 8; ++j) {
        const int tl = tt * 8 + j;
        rv[tl * 16 + tc] = bestv[j];
        ri[tl * 16 + tc] = besti[j];
    }
    __syncthreads();

    if (tid < TTILE) {
        float bv = -3.4e38f;
        int   bi = 0;
#pragma unroll
        for (int m = 0; m < 16; ++m) {
            float v = rv[tid * 16 + m];
            int   id = ri[tid * 16 + m];
            if (v > bv || (v == bv && id < bi)) { bv = v; bi = id; }
        }
        const int t = tb + tid;
        g_idx[(b * K_ + k) * T_ + t] = bi;
        atomicAdd(&g_counts[k * CS_ + bi], 1);
    }
}

// ---------- kernel B: codebook gather with smem transpose ----------
// grid: (T/64=32, K=8, B=8), 256 threads
__global__ void __launch_bounds__(256)
gather_kernel(const float* __restrict__ cb, float* __restrict__ out) {
    __shared__ float sm[CH_ * 65];   // [c][t], stride 65 -> conflict-free both phases
    __shared__ int sidx[64];

    const int tb  = blockIdx.x * 64;
    const int k   = blockIdx.y;
    const int b   = blockIdx.z;
    const int tid = threadIdx.x;

    if (tid < 64) sidx[tid] = g_idx[(b * K_ + k) * T_ + tb + tid];
    __syncthreads();

    // load 64 codebook rows, scatter-transpose into smem (conflict-free)
    {
        const int c = tid & 127;
        const int rh = tid >> 7;   // 0..1
#pragma unroll 4
        for (int it = 0; it < 32; ++it) {
            const int r = it * 2 + rh;
            float v = cb[((size_t)k * CS_ + sidx[r]) * CH_ + c];
            sm[c * 65 + r] = v;
        }
    }
    __syncthreads();

    // coalesced writes along t
    {
        const int t  = tid & 63;
        const int c0 = tid >> 6;   // 0..3
        float* og = out + ((size_t)b * DIM_ + (size_t)k * CH_) * T_ + tb + t;
#pragma unroll 8
        for (int m = 0; m < 32; ++m) {
            const int c = c0 * 32 + m;
            og[(size_t)c * T_] = sm[c * 65 + t];
        }
    }
}

// ---------- kernel C: perplexity ----------
__global__ void perplexity_kernel(float* __restrict__ out) {
    const int k = blockIdx.x;
    const int lane = threadIdx.x;
    float s = 0.0f;
    for (int i = lane; i < CS_; i += 32) {
        float p = (float)g_counts[k * CS_ + i] * (1.0f / (B_ * T_));
        s += -p * logf(p + 1e-8f);   // p==0 contributes exactly 0 (matches nansum)
    }
#pragma unroll
    for (int o = 16; o; o >>= 1) s += __shfl_down_sync(0xffffffffu, s, o);
    if (lane == 0) out[(size_t)B_ * DIM_ * T_ + k] = expf(s);
}

extern "C" void kernel_launch(void* const* d_in, const int* in_sizes, int n_in,
                              void* d_out, int out_size) {
    const float* x     = (const float*)d_in[0];
    const float* pw    = (const float*)d_in[1];
    const float* pb    = (const float*)d_in[2];
    const float* cbk   = (const float*)d_in[3];
    const float* noise = (const float*)d_in[4];
    float* out = (float*)d_out;

    const int smemA = (CH_ * TTILE + CSTILE * WS_STR) * (int)sizeof(float);  // 99,328 B
    cudaFuncSetAttribute(logits_argmax_kernel,
                         cudaFuncAttributeMaxDynamicSharedMemorySize, smemA);

    zero_counts_kernel<<<1, 256>>>();
    logits_argmax_kernel<<<dim3(T_ / TTILE, K_, B_), NTHR, smemA>>>(x, pw, pb, noise);
    gather_kernel<<<dim3(T_ / 64, K_, B_), 256>>>(cbk, out);
    perplexity_kernel<<<K_, 32>>>(out);
}

// round 4
// speedup vs baseline: 1.8418x; 1.1403x over previous
#include <cuda_runtime.h>
#include <cuda_bf16.h>
#include <cstdint>

#define B_   8
#define K_   8
#define T_   2048
#define CS_  512
#define CH_  128
#define DIM_ 1024

// ---------------- device scratch ----------------
__device__ int g_idx[B_ * K_ * T_];
__device__ int g_counts[K_ * CS_];
// W fragments: [k][mt(32)][kq(8)][lane(32)] uint4 = (a0,a1,a2,a3)
__device__ uint4 g_w0f[K_ * 32 * 8 * 32];
__device__ uint4 g_w1f[K_ * 32 * 8 * 32];
__device__ uint4 g_w2f[K_ * 32 * 8 * 32];
// X fragments: [bk(64)][kq(8)][ntile(256)][lane(32)] uint2 = (b0,b1)
__device__ uint2 g_x0f[(size_t)64 * 8 * 256 * 32];
__device__ uint2 g_x1f[(size_t)64 * 8 * 256 * 32];
__device__ uint2 g_x2f[(size_t)64 * 8 * 256 * 32];

// ---------------- helpers ----------------
__device__ __forceinline__ void split_pack(float x0, float x1,
                                           uint32_t& p0, uint32_t& p1, uint32_t& p2) {
    __nv_bfloat16 a0 = __float2bfloat16(x0), b0 = __float2bfloat16(x1);
    float r0 = x0 - __bfloat162float(a0), s0 = x1 - __bfloat162float(b0);
    __nv_bfloat16 a1 = __float2bfloat16(r0), b1 = __float2bfloat16(s0);
    float r1 = r0 - __bfloat162float(a1), s1 = s0 - __bfloat162float(b1);
    __nv_bfloat16 a2 = __float2bfloat16(r1), b2 = __float2bfloat16(s1);
    p0 = ((uint32_t)(*(uint16_t*)&b0) << 16) | *(uint16_t*)&a0;
    p1 = ((uint32_t)(*(uint16_t*)&b1) << 16) | *(uint16_t*)&a1;
    p2 = ((uint32_t)(*(uint16_t*)&b2) << 16) | *(uint16_t*)&a2;
}

__device__ __forceinline__ float gum(float u) {
    return -logf(-logf(u + 1e-10f) + 1e-10f);
}

__device__ __forceinline__ void mma16816(float* c, const uint4& A, const uint2& Bf) {
    asm volatile(
        "mma.sync.aligned.m16n8k16.row.col.f32.bf16.bf16.f32 "
        "{%0,%1,%2,%3},{%4,%5,%6,%7},{%8,%9},{%0,%1,%2,%3};"
        : "+f"(c[0]), "+f"(c[1]), "+f"(c[2]), "+f"(c[3])
        : "r"(A.x), "r"(A.y), "r"(A.z), "r"(A.w), "r"(Bf.x), "r"(Bf.y));
}

// ---------------- kernel: zero ----------------
__global__ void zero_counts_kernel() {
    for (int i = threadIdx.x; i < K_ * CS_; i += blockDim.x) g_counts[i] = 0;
}

// ---------------- kernel: W -> fragment splits ----------------
// grid (32 mt, 8 k), 256 thr
__global__ void __launch_bounds__(256) wsplit_kernel(const float* __restrict__ pw) {
    const int mt = blockIdx.x, k = blockIdx.y;
    const int tid = threadIdx.x, kq = tid >> 5, lane = tid & 31;
    const int g = lane >> 2, tg = lane & 3;
    const float* base = pw + ((size_t)(k * CS_ + mt * 16)) * CH_;
    const int ch0 = kq * 16 + 2 * tg;

    float v[4][2];
    v[0][0] = base[g * CH_ + ch0];           v[0][1] = base[g * CH_ + ch0 + 1];
    v[1][0] = base[(g + 8) * CH_ + ch0];     v[1][1] = base[(g + 8) * CH_ + ch0 + 1];
    v[2][0] = base[g * CH_ + ch0 + 8];       v[2][1] = base[g * CH_ + ch0 + 9];
    v[3][0] = base[(g + 8) * CH_ + ch0 + 8]; v[3][1] = base[(g + 8) * CH_ + ch0 + 9];

    uint32_t q[4][3];
#pragma unroll
    for (int i = 0; i < 4; ++i) split_pack(v[i][0], v[i][1], q[i][0], q[i][1], q[i][2]);

    const size_t o = ((size_t)(k * 32 + mt) * 8 + kq) * 32 + lane;
    g_w0f[o] = make_uint4(q[0][0], q[1][0], q[2][0], q[3][0]);
    g_w1f[o] = make_uint4(q[0][1], q[1][1], q[2][1], q[3][1]);
    g_w2f[o] = make_uint4(q[0][2], q[1][2], q[2][2], q[3][2]);
}

// ---------------- kernel: X -> fragment splits (with transpose) ----------------
// grid (16 tt, 8 k, 8 b), 256 thr, smem 128*132*4
__global__ void __launch_bounds__(256) xsplit_kernel(const float* __restrict__ x) {
    extern __shared__ float st[];   // [128 c][132]
    const int tt = blockIdx.x, k = blockIdx.y, b = blockIdx.z;
    const int tid = threadIdx.x;
    {
        const int c = tid >> 1, toff = (tid & 1) * 64;
        const float* src = x + ((size_t)(b * DIM_ + k * CH_ + c)) * T_ + tt * 128 + toff;
#pragma unroll
        for (int j = 0; j < 16; ++j)
            *(float4*)&st[c * 132 + toff + 4 * j] = *(const float4*)(src + 4 * j);
    }
    __syncthreads();
    const int kq = tid >> 5, lane = tid & 31, g = lane >> 2, tg = lane & 3;
    const int bk = b * K_ + k;
    const size_t obase = ((size_t)(bk * 8 + kq) * 256 + tt * 16) * 32 + lane;
    const int r0 = kq * 16 + 2 * tg;
#pragma unroll
    for (int nt = 0; nt < 16; ++nt) {
        const int tl = nt * 8 + g;
        float v0 = st[r0 * 132 + tl],       v1 = st[(r0 + 1) * 132 + tl];
        float v8 = st[(r0 + 8) * 132 + tl], v9 = st[(r0 + 9) * 132 + tl];
        uint32_t p0a, p0b, p0c, p1a, p1b, p1c;
        split_pack(v0, v1, p0a, p0b, p0c);
        split_pack(v8, v9, p1a, p1b, p1c);
        const size_t o = obase + nt * 32;
        g_x0f[o] = make_uint2(p0a, p1a);
        g_x1f[o] = make_uint2(p0b, p1b);
        g_x2f[o] = make_uint2(p0c, p1c);
    }
}

// ---------------- main kernel ----------------
template<int NX>
__device__ __forceinline__ void gemm_pass(const uint4* __restrict__ gw,
                                          const uint2* __restrict__ sx,
                                          float acc[64], int kb, int lane, int wn) {
#pragma unroll
    for (int kq = 0; kq < 8; ++kq) {
        uint4 A0 = gw[kb + kq * 32 + lane];
        uint4 A1 = gw[kb + 256 + kq * 32 + lane];
#pragma unroll
        for (int xj = 0; xj < NX; ++xj) {
            const uint2* bp = sx + (size_t)(xj * 8 + kq) * 512 + wn * 256 + lane;
#pragma unroll
            for (int j = 0; j < 8; ++j) {
                uint2 Bf = bp[j * 32];
                mma16816(&acc[j * 4], A0, Bf);
                mma16816(&acc[32 + j * 4], A1, Bf);
            }
        }
    }
}

// smem: [0, 98304) X frags (reused as reduce buf), [98304, 100352) pb
__global__ void __launch_bounds__(256)
main_kernel(const float* __restrict__ pb, const float* __restrict__ noise) {
    extern __shared__ char smc[];
    uint2* sx = (uint2*)smc;
    float* s_pb = (float*)(smc + 98304);

    const int tid = threadIdx.x, wid = tid >> 5, lane = tid & 31;
    const int g = lane >> 2, tg = lane & 3;
    const int wm = wid & 3, wn = wid >> 2;
    const int tt = blockIdx.x, k = blockIdx.y, b = blockIdx.z;
    const int bk = b * K_ + k;

    for (int idx = tid; idx < 12288; idx += 256) {
        const int s = idx >> 12, rem = idx & 4095, kq = rem >> 9, r = rem & 511;
        const uint2* src = (s == 0) ? g_x0f : (s == 1) ? g_x1f : g_x2f;
        sx[(s * 8 + kq) * 512 + r] = src[((size_t)(bk * 8 + kq) * 256 + tt * 16) * 32 + r];
    }
    for (int i = tid; i < 512; i += 256) s_pb[i] = pb[k * CS_ + i];
    __syncthreads();

    float bestv[16];
    int   besti[16];
#pragma unroll
    for (int j = 0; j < 16; ++j) { bestv[j] = -3.4e38f; besti[j] = 0; }

    const float* nbase = noise + (size_t)bk * CS_ * T_ + tt * 128 + wn * 64 + 2 * tg;

    for (int m = 0; m < 4; ++m) {
        float acc[64];
#pragma unroll
        for (int i = 0; i < 64; ++i) acc[i] = 0.0f;

        const int kb = (k * 32 + m * 8 + wm * 2) * 256;
        gemm_pass<3>(g_w0f, sx, acc, kb, lane, wn);
        gemm_pass<2>(g_w1f, sx, acc, kb, lane, wn);
        gemm_pass<1>(g_w2f, sx, acc, kb, lane, wn);

#pragma unroll
        for (int i = 0; i < 2; ++i) {
            const int cs0 = m * 128 + wm * 32 + i * 16 + g;
            const float bb0 = s_pb[cs0], bb1 = s_pb[cs0 + 8];
#pragma unroll
            for (int j = 0; j < 8; ++j) {
                float2 n0 = *(const float2*)(nbase + (size_t)cs0 * T_ + j * 8);
                float2 n1 = *(const float2*)(nbase + (size_t)(cs0 + 8) * T_ + j * 8);
                float v00 = acc[i * 32 + j * 4 + 0] + bb0 + gum(n0.x);
                float v01 = acc[i * 32 + j * 4 + 1] + bb0 + gum(n0.y);
                float v10 = acc[i * 32 + j * 4 + 2] + bb1 + gum(n1.x);
                float v11 = acc[i * 32 + j * 4 + 3] + bb1 + gum(n1.y);
                const int c0 = j * 2, c1 = j * 2 + 1;
                if (v00 > bestv[c0]) { bestv[c0] = v00; besti[c0] = cs0; }
                if (v10 > bestv[c0]) { bestv[c0] = v10; besti[c0] = cs0 + 8; }
                if (v01 > bestv[c1]) { bestv[c1] = v01; besti[c1] = cs0; }
                if (v11 > bestv[c1]) { bestv[c1] = v11; besti[c1] = cs0 + 8; }
            }
        }
    }

    __syncthreads();
    float* cv = (float*)smc;                 // [128 t][32 slot]
    int*   ci = (int*)(smc + 16384);
    const int slot = wm * 8 + g;
#pragma unroll
    for (int j = 0; j < 16; ++j) {
        const int tl = wn * 64 + (j >> 1) * 8 + 2 * tg + (j & 1);
        cv[tl * 32 + slot] = bestv[j];
        ci[tl * 32 + slot] = besti[j];
    }
    __syncthreads();
    if (tid < 128) {
        float fv = -3.4e38f; int fi = 0;
#pragma unroll
        for (int s2 = 0; s2 < 32; ++s2) {
            float v = cv[tid * 32 + s2];
            int id = ci[tid * 32 + s2];
            if (v > fv || (v == fv && id < fi)) { fv = v; fi = id; }
        }
        g_idx[bk * T_ + tt * 128 + tid] = fi;
        atomicAdd(&g_counts[k * CS_ + fi], 1);
    }
}

// ---------------- gather ----------------
__global__ void __launch_bounds__(256)
gather_kernel(const float* __restrict__ cb, float* __restrict__ out) {
    __shared__ float sm[CH_ * 65];
    __shared__ int sidx[64];
    const int tb = blockIdx.x * 64, k = blockIdx.y, b = blockIdx.z;
    const int tid = threadIdx.x;
    if (tid < 64) sidx[tid] = g_idx[(b * K_ + k) * T_ + tb + tid];
    __syncthreads();
    {
        const int c = tid & 127, rh = tid >> 7;
#pragma unroll 4
        for (int it = 0; it < 32; ++it) {
            const int r = it * 2 + rh;
            sm[c * 65 + r] = cb[((size_t)k * CS_ + sidx[r]) * CH_ + c];
        }
    }
    __syncthreads();
    {
        const int t = tid & 63, c0 = tid >> 6;
        float* og = out + ((size_t)b * DIM_ + (size_t)k * CH_) * T_ + tb + t;
#pragma unroll 8
        for (int mth = 0; mth < 32; ++mth) {
            const int c = c0 * 32 + mth;
            og[(size_t)c * T_] = sm[c * 65 + t];
        }
    }
}

// ---------------- perplexity (one block, warp per k) ----------------
__global__ void perplexity_kernel(float* __restrict__ out) {
    const int k = threadIdx.x >> 5, lane = threadIdx.x & 31;
    float s = 0.0f;
    for (int i = lane; i < CS_; i += 32) {
        float p = (float)g_counts[k * CS_ + i] * (1.0f / (B_ * T_));
        s += -p * logf(p + 1e-8f);
    }
#pragma unroll
    for (int o = 16; o; o >>= 1) s += __shfl_down_sync(0xffffffffu, s, o);
    if (lane == 0) out[(size_t)B_ * DIM_ * T_ + k] = expf(s);
}

extern "C" void kernel_launch(void* const* d_in, const int* in_sizes, int n_in,
                              void* d_out, int out_size) {
    const float* x     = (const float*)d_in[0];
    const float* pw    = (const float*)d_in[1];
    const float* pb    = (const float*)d_in[2];
    const float* cbk   = (const float*)d_in[3];
    const float* noise = (const float*)d_in[4];
    float* out = (float*)d_out;

    cudaFuncSetAttribute(xsplit_kernel, cudaFuncAttributeMaxDynamicSharedMemorySize, 128 * 132 * 4);
    cudaFuncSetAttribute(main_kernel, cudaFuncAttributeMaxDynamicSharedMemorySize, 100352);

    zero_counts_kernel<<<1, 256>>>();
    wsplit_kernel<<<dim3(32, K_), 256>>>(pw);
    xsplit_kernel<<<dim3(16, K_, B_), 256, 128 * 132 * 4>>>(x);
    main_kernel<<<dim3(16, K_, B_), 256, 100352>>>(pb, noise);
    gather_kernel<<<dim3(T_ / 64, K_, B_), 256>>>(cbk, out);
    perplexity_kernel<<<1, 256>>>(out);
}

// round 5
// speedup vs baseline: 2.2959x; 1.2465x over previous
#include <cuda_runtime.h>
#include <cuda_bf16.h>
#include <cstdint>

#define B_   8
#define K_   8
#define T_   2048
#define CS_  512
#define CH_  128
#define DIM_ 1024

// ---------------- device scratch ----------------
__device__ int g_idx[B_ * K_ * T_];
__device__ int g_counts[K_ * CS_];
// W fragments: [k][mt(32)][kq(8)][lane(32)] uint4 = (a0,a1,a2,a3)
__device__ uint4 g_w0f[K_ * 32 * 8 * 32];
__device__ uint4 g_w1f[K_ * 32 * 8 * 32];
__device__ uint4 g_w2f[K_ * 32 * 8 * 32];
// X fragments: [bk(64)][kq(8)][ntile(256)][lane(32)] uint2 = (b0,b1)
__device__ uint2 g_x0f[(size_t)64 * 8 * 256 * 32];
__device__ uint2 g_x1f[(size_t)64 * 8 * 256 * 32];
__device__ uint2 g_x2f[(size_t)64 * 8 * 256 * 32];

// ---------------- helpers ----------------
__device__ __forceinline__ void split_pack(float x0, float x1,
                                           uint32_t& p0, uint32_t& p1, uint32_t& p2) {
    __nv_bfloat16 a0 = __float2bfloat16(x0), b0 = __float2bfloat16(x1);
    float r0 = x0 - __bfloat162float(a0), s0 = x1 - __bfloat162float(b0);
    __nv_bfloat16 a1 = __float2bfloat16(r0), b1 = __float2bfloat16(s0);
    float r1 = r0 - __bfloat162float(a1), s1 = s0 - __bfloat162float(b1);
    __nv_bfloat16 a2 = __float2bfloat16(r1), b2 = __float2bfloat16(s1);
    p0 = ((uint32_t)(*(uint16_t*)&b0) << 16) | *(uint16_t*)&a0;
    p1 = ((uint32_t)(*(uint16_t*)&b1) << 16) | *(uint16_t*)&a1;
    p2 = ((uint32_t)(*(uint16_t*)&b2) << 16) | *(uint16_t*)&a2;
}

__device__ __forceinline__ float gum(float u) {
    return -logf(-logf(u + 1e-10f) + 1e-10f);
}

__device__ __forceinline__ void mma16816(float* c, const uint4& A, const uint2& Bf) {
    asm volatile(
        "mma.sync.aligned.m16n8k16.row.col.f32.bf16.bf16.f32 "
        "{%0,%1,%2,%3},{%4,%5,%6,%7},{%8,%9},{%0,%1,%2,%3};"
        : "+f"(c[0]), "+f"(c[1]), "+f"(c[2]), "+f"(c[3])
        : "r"(A.x), "r"(A.y), "r"(A.z), "r"(A.w), "r"(Bf.x), "r"(Bf.y));
}

// ---------------- kernel: zero ----------------
__global__ void zero_counts_kernel() {
    for (int i = threadIdx.x; i < K_ * CS_; i += blockDim.x) g_counts[i] = 0;
}

// ---------------- kernel: W -> fragment splits ----------------
__global__ void __launch_bounds__(256) wsplit_kernel(const float* __restrict__ pw) {
    const int mt = blockIdx.x, k = blockIdx.y;
    const int tid = threadIdx.x, kq = tid >> 5, lane = tid & 31;
    const int g = lane >> 2, tg = lane & 3;
    const float* base = pw + ((size_t)(k * CS_ + mt * 16)) * CH_;
    const int ch0 = kq * 16 + 2 * tg;

    float v[4][2];
    v[0][0] = base[g * CH_ + ch0];           v[0][1] = base[g * CH_ + ch0 + 1];
    v[1][0] = base[(g + 8) * CH_ + ch0];     v[1][1] = base[(g + 8) * CH_ + ch0 + 1];
    v[2][0] = base[g * CH_ + ch0 + 8];       v[2][1] = base[g * CH_ + ch0 + 9];
    v[3][0] = base[(g + 8) * CH_ + ch0 + 8]; v[3][1] = base[(g + 8) * CH_ + ch0 + 9];

    uint32_t q[4][3];
#pragma unroll
    for (int i = 0; i < 4; ++i) split_pack(v[i][0], v[i][1], q[i][0], q[i][1], q[i][2]);

    const size_t o = ((size_t)(k * 32 + mt) * 8 + kq) * 32 + lane;
    g_w0f[o] = make_uint4(q[0][0], q[1][0], q[2][0], q[3][0]);
    g_w1f[o] = make_uint4(q[0][1], q[1][1], q[2][1], q[3][1]);
    g_w2f[o] = make_uint4(q[0][2], q[1][2], q[2][2], q[3][2]);
}

// ---------------- kernel: X -> fragment splits (with transpose) ----------------
__global__ void __launch_bounds__(256) xsplit_kernel(const float* __restrict__ x) {
    extern __shared__ float st[];   // [128 c][132]
    const int tt = blockIdx.x, k = blockIdx.y, b = blockIdx.z;
    const int tid = threadIdx.x;
    {
        const int c = tid >> 1, toff = (tid & 1) * 64;
        const float* src = x + ((size_t)(b * DIM_ + k * CH_ + c)) * T_ + tt * 128 + toff;
#pragma unroll
        for (int j = 0; j < 16; ++j)
            *(float4*)&st[c * 132 + toff + 4 * j] = *(const float4*)(src + 4 * j);
    }
    __syncthreads();
    const int kq = tid >> 5, lane = tid & 31, g = lane >> 2, tg = lane & 3;
    const int bk = b * K_ + k;
    const size_t obase = ((size_t)(bk * 8 + kq) * 256 + tt * 16) * 32 + lane;
    const int r0 = kq * 16 + 2 * tg;
#pragma unroll
    for (int nt = 0; nt < 16; ++nt) {
        const int tl = nt * 8 + g;
        float v0 = st[r0 * 132 + tl],       v1 = st[(r0 + 1) * 132 + tl];
        float v8 = st[(r0 + 8) * 132 + tl], v9 = st[(r0 + 9) * 132 + tl];
        uint32_t p0a, p0b, p0c, p1a, p1b, p1c;
        split_pack(v0, v1, p0a, p0b, p0c);
        split_pack(v8, v9, p1a, p1b, p1c);
        const size_t o = obase + nt * 32;
        g_x0f[o] = make_uint2(p0a, p1a);
        g_x1f[o] = make_uint2(p0b, p1b);
        g_x2f[o] = make_uint2(p0c, p1c);
    }
}

// ---------------- main kernel ----------------
// smem: [0, 98304) X frags; [98304, 100352) pb; [100352, 102400) redv; [102400, 104448) redi
#define SM_PB   98304
#define SM_RV   100352
#define SM_RI   102400
#define SM_TOT  104448

__global__ void __launch_bounds__(256, 2)
main_kernel(const float* __restrict__ pb, const float* __restrict__ noise) {
    extern __shared__ char smc[];
    uint2* sx = (uint2*)smc;
    float* s_pb = (float*)(smc + SM_PB);
    float* redv = (float*)(smc + SM_RV);
    int*   redi = (int*)(smc + SM_RI);

    const int tid = threadIdx.x, wid = tid >> 5, lane = tid & 31;
    const int g = lane >> 2, tg = lane & 3;
    const int wm = wid & 3, wn = wid >> 2;
    const int tt = blockIdx.x, k = blockIdx.y, b = blockIdx.z;
    const int bk = b * K_ + k;

    for (int idx = tid; idx < 12288; idx += 256) {
        const int s = idx >> 12, rem = idx & 4095, kq = rem >> 9, r = rem & 511;
        const uint2* src = (s == 0) ? g_x0f : (s == 1) ? g_x1f : g_x2f;
        sx[(s * 8 + kq) * 512 + r] = src[((size_t)(bk * 8 + kq) * 256 + tt * 16) * 32 + r];
    }
    for (int i = tid; i < 512; i += 256) {
        s_pb[i] = pb[k * CS_ + i];
        redv[i] = -3.4e38f;
        redi[i] = 0;
    }
    __syncthreads();

    const float* nbase = noise + (size_t)bk * CS_ * T_ + tt * 128 + wn * 64 + 2 * tg;

    for (int m = 0; m < 4; ++m) {
        float acc[64];
#pragma unroll
        for (int i = 0; i < 64; ++i) acc[i] = 0.0f;

        const int kb = (k * 32 + m * 8 + wm * 2) * 256 + lane;
        const uint2* bp0 = sx + wn * 256 + lane;

#pragma unroll
        for (int kq = 0; kq < 8; ++kq) {
            const int ai = kb + kq * 32;
            uint4 a00 = g_w0f[ai], a01 = g_w0f[ai + 256];
            uint4 a10 = g_w1f[ai], a11 = g_w1f[ai + 256];
            uint4 a20 = g_w2f[ai], a21 = g_w2f[ai + 256];
            const uint2* bq = bp0 + kq * 512;
#pragma unroll
            for (int j = 0; j < 8; ++j) {
                uint2 b0 = bq[j * 32];
                uint2 b1 = bq[4096 + j * 32];
                uint2 b2 = bq[8192 + j * 32];
                float* c0 = &acc[j * 4];
                float* c1 = &acc[32 + j * 4];
                mma16816(c0, a00, b0); mma16816(c1, a01, b0);
                mma16816(c0, a10, b0); mma16816(c1, a11, b0);
                mma16816(c0, a20, b0); mma16816(c1, a21, b0);
                mma16816(c0, a00, b1); mma16816(c1, a01, b1);
                mma16816(c0, a10, b1); mma16816(c1, a11, b1);
                mma16816(c0, a00, b2); mma16816(c1, a01, b2);
            }
        }

        // ---- epilogue: bias + gumbel + warp argmax (shfl over g-lanes) ----
        const int cs0 = m * 128 + wm * 32 + g;
        const float bb0 = s_pb[cs0],      bb1 = s_pb[cs0 + 8];
        const float bb2 = s_pb[cs0 + 16], bb3 = s_pb[cs0 + 24];
        const float* nrow = nbase + (size_t)cs0 * T_;
#pragma unroll
        for (int j = 0; j < 8; ++j) {
            float2 n0 = *(const float2*)(nrow + j * 8);
            float2 n1 = *(const float2*)(nrow + (size_t)8 * T_ + j * 8);
            float2 n2 = *(const float2*)(nrow + (size_t)16 * T_ + j * 8);
            float2 n3 = *(const float2*)(nrow + (size_t)24 * T_ + j * 8);
            float va0 = acc[j * 4 + 0] + bb0 + gum(n0.x);
            float va1 = acc[j * 4 + 1] + bb0 + gum(n0.y);
            float vb0 = acc[j * 4 + 2] + bb1 + gum(n1.x);
            float vb1 = acc[j * 4 + 3] + bb1 + gum(n1.y);
            float vc0 = acc[32 + j * 4 + 0] + bb2 + gum(n2.x);
            float vc1 = acc[32 + j * 4 + 1] + bb2 + gum(n2.y);
            float vd0 = acc[32 + j * 4 + 2] + bb3 + gum(n3.x);
            float vd1 = acc[32 + j * 4 + 3] + bb3 + gum(n3.y);
#pragma unroll
            for (int c = 0; c < 2; ++c) {
                float bv = c ? va1 : va0; int bi = cs0;
                float v1c = c ? vb1 : vb0;
                float v2c = c ? vc1 : vc0;
                float v3c = c ? vd1 : vd0;
                if (v1c > bv) { bv = v1c; bi = cs0 + 8; }
                if (v2c > bv) { bv = v2c; bi = cs0 + 16; }
                if (v3c > bv) { bv = v3c; bi = cs0 + 24; }
#pragma unroll
                for (int msk = 4; msk <= 16; msk <<= 1) {
                    float ov = __shfl_xor_sync(0xffffffffu, bv, msk);
                    int   oi = __shfl_xor_sync(0xffffffffu, bi, msk);
                    if (ov > bv || (ov == bv && oi < bi)) { bv = ov; bi = oi; }
                }
                if (lane < 4) {
                    const int tl = wn * 64 + j * 8 + 2 * tg + c;
                    const int slot = tl * 4 + wm;
                    float cv = redv[slot];
                    int   ci = redi[slot];
                    if (bv > cv || (bv == cv && bi < ci)) { redv[slot] = bv; redi[slot] = bi; }
                }
            }
        }
    }

    __syncthreads();
    if (tid < 128) {
        float fv = -3.4e38f; int fi = 0;
#pragma unroll
        for (int s2 = 0; s2 < 4; ++s2) {
            float v = redv[tid * 4 + s2];
            int id = redi[tid * 4 + s2];
            if (v > fv || (v == fv && id < fi)) { fv = v; fi = id; }
        }
        g_idx[bk * T_ + tt * 128 + tid] = fi;
        atomicAdd(&g_counts[k * CS_ + fi], 1);
    }
}

// ---------------- gather ----------------
__global__ void __launch_bounds__(256)
gather_kernel(const float* __restrict__ cb, float* __restrict__ out) {
    __shared__ float sm[CH_ * 65];
    __shared__ int sidx[64];
    const int tb = blockIdx.x * 64, k = blockIdx.y, b = blockIdx.z;
    const int tid = threadIdx.x;
    if (tid < 64) sidx[tid] = g_idx[(b * K_ + k) * T_ + tb + tid];
    __syncthreads();
    {
        const int c = tid & 127, rh = tid >> 7;
#pragma unroll 4
        for (int it = 0; it < 32; ++it) {
            const int r = it * 2 + rh;
            sm[c * 65 + r] = cb[((size_t)k * CS_ + sidx[r]) * CH_ + c];
        }
    }
    __syncthreads();
    {
        const int t = tid & 63, c0 = tid >> 6;
        float* og = out + ((size_t)b * DIM_ + (size_t)k * CH_) * T_ + tb + t;
#pragma unroll 8
        for (int mth = 0; mth < 32; ++mth) {
            const int c = c0 * 32 + mth;
            og[(size_t)c * T_] = sm[c * 65 + t];
        }
    }
}

// ---------------- perplexity ----------------
__global__ void perplexity_kernel(float* __restrict__ out) {
    const int k = threadIdx.x >> 5, lane = threadIdx.x & 31;
    float s = 0.0f;
    for (int i = lane; i < CS_; i += 32) {
        float p = (float)g_counts[k * CS_ + i] * (1.0f / (B_ * T_));
        s += -p * logf(p + 1e-8f);
    }
#pragma unroll
    for (int o = 16; o; o >>= 1) s += __shfl_down_sync(0xffffffffu, s, o);
    if (lane == 0) out[(size_t)B_ * DIM_ * T_ + k] = expf(s);
}

extern "C" void kernel_launch(void* const* d_in, const int* in_sizes, int n_in,
                              void* d_out, int out_size) {
    const float* x     = (const float*)d_in[0];
    const float* pw    = (const float*)d_in[1];
    const float* pb    = (const float*)d_in[2];
    const float* cbk   = (const float*)d_in[3];
    const float* noise = (const float*)d_in[4];
    float* out = (float*)d_out;

    cudaFuncSetAttribute(xsplit_kernel, cudaFuncAttributeMaxDynamicSharedMemorySize, 128 * 132 * 4);
    cudaFuncSetAttribute(main_kernel, cudaFuncAttributeMaxDynamicSharedMemorySize, SM_TOT);

    zero_counts_kernel<<<1, 256>>>();
    wsplit_kernel<<<dim3(32, K_), 256>>>(pw);
    xsplit_kernel<<<dim3(16, K_, B_), 256, 128 * 132 * 4>>>(x);
    main_kernel<<<dim3(16, K_, B_), 256, SM_TOT>>>(pb, noise);
    gather_kernel<<<dim3(T_ / 64, K_, B_), 256>>>(cbk, out);
    perplexity_kernel<<<1, 256>>>(out);
}